// round 6
// baseline (speedup 1.0000x reference)
#include <cuda_runtime.h>
#include <cuda_fp16.h>

#define DDIM    256
#define NMAX    8192
#define LISTCAP 768     // mean nnz ~164, sd ~12.7; 768 is absurdly safe
#define BW      4       // per-warp batch in phase B

// Scratch: normalized y rows in fp16 (4 MB, L2-resident) + row norms (fp32).
__device__ __half2 g_yn[(size_t)NMAX * (DDIM / 2)];
__device__ float   g_ynorm[NMAX];

__device__ __forceinline__ float warp_sum(float v) {
#pragma unroll
    for (int off = 16; off; off >>= 1)
        v += __shfl_xor_sync(0xffffffffu, v, off);
    return v;
}

// One warp per y row: compute norm, store fp16 normalized copy + norm scalar.
__global__ void __launch_bounds__(256) prep_y(const float* __restrict__ y, int M) {
    int w    = (blockIdx.x * blockDim.x + threadIdx.x) >> 5;
    int lane = threadIdx.x & 31;
    if (w >= M) return;

    const float4* yp = (const float4*)(y + (size_t)w * DDIM);
    float4 a = yp[lane * 2];
    float4 b = yp[lane * 2 + 1];
    float ss = a.x * a.x + a.y * a.y + a.z * a.z + a.w * a.w
             + b.x * b.x + b.y * b.y + b.z * b.z + b.w * b.w;
    ss = warp_sum(ss);
    float n   = fmaxf(sqrtf(ss), 1e-8f);   // matches max(norm, EPS)
    float inv = 1.0f / n;
    if (lane == 0) g_ynorm[w] = n;

    __half2* o = g_yn + (size_t)w * (DDIM / 2) + lane * 4;
    o[0] = __floats2half2_rn(a.x * inv, a.y * inv);
    o[1] = __floats2half2_rn(a.z * inv, a.w * inv);
    o[2] = __floats2half2_rn(b.x * inv, b.y * inv);
    o[3] = __floats2half2_rn(b.z * inv, b.w * inv);
}

// One CTA (256 threads, 8 warps) per output row.
// Phase A: 8 warps scan disjoint adj segments, 8 float4 loads in flight each,
//          compact nonzero indices into a shared list (order-scrambled — fine).
// Phase B: warps split the neighbor list (batch 4), packed 6-SHFL reduction,
//          cross-warp combine through smem.
__global__ void __launch_bounds__(256) gat_main(const float* __restrict__ x,
                                                const float* __restrict__ adj,
                                                float* __restrict__ out,
                                                int N, int M) {
    __shared__ unsigned short s_list[LISTCAP];
    __shared__ float s_o[8][DDIM];
    __shared__ float s_l[8];
    __shared__ int   s_cnt;

    const int i    = blockIdx.x;
    const int tid  = threadIdx.x;
    const int wib  = tid >> 5;
    const int lane = tid & 31;

    if (tid == 0) s_cnt = 0;
    __syncthreads();

    // ---- Per-warp: load + normalize x row (lane owns dims [8l, 8l+8)) ----
    const float4* xp = (const float4*)(x + (size_t)i * DDIM);
    float4 xa = xp[lane * 2];
    float4 xb = xp[lane * 2 + 1];
    float ss = xa.x * xa.x + xa.y * xa.y + xa.z * xa.z + xa.w * xa.w
             + xb.x * xb.x + xb.y * xb.y + xb.z * xb.z + xb.w * xb.w;
    ss = warp_sum(ss);
    float xinv = 1.0f / fmaxf(sqrtf(ss), 1e-8f);

    __half2 xh0 = __floats2half2_rn(xa.x * xinv, xa.y * xinv);
    __half2 xh1 = __floats2half2_rn(xa.z * xinv, xa.w * xinv);
    __half2 xh2 = __floats2half2_rn(xb.x * xinv, xb.y * xinv);
    __half2 xh3 = __floats2half2_rn(xb.z * xinv, xb.w * xinv);

    // ---- Phase A: segment scan with 8 loads in flight per warp ----
    const float* arow = adj + (size_t)i * M;
    const unsigned lt = (1u << lane) - 1u;

    for (int seg = wib * 1024; seg < M; seg += 8 * 1024) {
        float4 a[8];
#pragma unroll
        for (int u = 0; u < 8; ++u)
            a[u] = __ldcs((const float4*)(arow + seg + u * 128 + lane * 4));

#pragma unroll
        for (int u = 0; u < 8; ++u) {
            int jb = seg + u * 128 + lane * 4;
            unsigned m0 = __ballot_sync(0xffffffffu, a[u].x != 0.f);
            unsigned m1 = __ballot_sync(0xffffffffu, a[u].y != 0.f);
            unsigned m2 = __ballot_sync(0xffffffffu, a[u].z != 0.f);
            unsigned m3 = __ballot_sync(0xffffffffu, a[u].w != 0.f);
            int c0 = __popc(m0), c1 = __popc(m1), c2 = __popc(m2), c3 = __popc(m3);
            int tot = c0 + c1 + c2 + c3;
            int base = 0;
            if (tot) {
                if (lane == 0) base = atomicAdd(&s_cnt, tot);
                base = __shfl_sync(0xffffffffu, base, 0);
                if (a[u].x != 0.f) s_list[base + __popc(m0 & lt)]                = (unsigned short)(jb);
                if (a[u].y != 0.f) s_list[base + c0 + __popc(m1 & lt)]           = (unsigned short)(jb + 1);
                if (a[u].z != 0.f) s_list[base + c0 + c1 + __popc(m2 & lt)]      = (unsigned short)(jb + 2);
                if (a[u].w != 0.f) s_list[base + c0 + c1 + c2 + __popc(m3 & lt)] = (unsigned short)(jb + 3);
            }
        }
    }
    __syncthreads();
    const int cnt = s_cnt;

    // ---- Phase B: warps split neighbor list, batch 4 ----
    float o0 = 0.f, o1 = 0.f, o2 = 0.f, o3 = 0.f;
    float o4 = 0.f, o5 = 0.f, o6 = 0.f, o7 = 0.f;
    float l = 0.f;

    const bool lo16 = (lane & 16) == 0;
    const bool lo8  = (lane & 8)  == 0;

    for (int base = wib * BW; base < cnt; base += 8 * BW) {
        int   jj[BW];
        uint4 v[BW];
        float d[BW], yn[BW];

        // 4 outstanding 16B L2 loads
#pragma unroll
        for (int k = 0; k < BW; ++k) {
            int idx = base + k;
            jj[k] = s_list[idx < cnt ? idx : 0];
            v[k] = *(const uint4*)(g_yn + (size_t)jj[k] * (DDIM / 2) + lane * 4);
        }
#pragma unroll
        for (int k = 0; k < BW; ++k)
            yn[k] = __ldg(&g_ynorm[jj[k]]);

        // 4 independent partial dots
#pragma unroll
        for (int k = 0; k < BW; ++k) {
            __half2 acc = __hmul2(xh0, *(const __half2*)&v[k].x);
            acc = __hfma2(xh1, *(const __half2*)&v[k].y, acc);
            acc = __hfma2(xh2, *(const __half2*)&v[k].z, acc);
            acc = __hfma2(xh3, *(const __half2*)&v[k].w, acc);
            float2 af = __half22float2(acc);
            d[k] = af.x + af.y;
        }

        // Packed 4-value reduction: 6 SHFLs. Value k ends in lane group 8k.
#pragma unroll
        for (int k = 0; k < 2; ++k) {
            float send = lo16 ? d[k + 2] : d[k];
            float recv = __shfl_xor_sync(0xffffffffu, send, 16);
            d[k] = (lo16 ? d[k] : d[k + 2]) + recv;
        }
        {
            float send = lo8 ? d[1] : d[0];
            float recv = __shfl_xor_sync(0xffffffffu, send, 8);
            d[0] = (lo8 ? d[0] : d[1]) + recv;
        }
        d[0] += __shfl_xor_sync(0xffffffffu, d[0], 4);
        d[0] += __shfl_xor_sync(0xffffffffu, d[0], 2);
        d[0] += __shfl_xor_sync(0xffffffffu, d[0], 1);

        float e = __expf(d[0] - 1.0f);   // one MUFU per batch

#pragma unroll
        for (int k = 0; k < BW; ++k) {
            float ek = __shfl_sync(0xffffffffu, e, 8 * k);
            float p  = (base + k < cnt) ? ek : 0.f;
            l += p;
            float q = p * yn[k];
            float2 f0 = __half22float2(*(const __half2*)&v[k].x);
            float2 f1 = __half22float2(*(const __half2*)&v[k].y);
            float2 f2 = __half22float2(*(const __half2*)&v[k].z);
            float2 f3 = __half22float2(*(const __half2*)&v[k].w);
            o0 = fmaf(q, f0.x, o0);
            o1 = fmaf(q, f0.y, o1);
            o2 = fmaf(q, f1.x, o2);
            o3 = fmaf(q, f1.y, o3);
            o4 = fmaf(q, f2.x, o4);
            o5 = fmaf(q, f2.y, o5);
            o6 = fmaf(q, f3.x, o6);
            o7 = fmaf(q, f3.y, o7);
        }
    }

    // ---- Cross-warp combine ----
    float* so = s_o[wib] + lane * 8;
    so[0] = o0; so[1] = o1; so[2] = o2; so[3] = o3;
    so[4] = o4; so[5] = o5; so[6] = o6; so[7] = o7;
    if (lane == 0) s_l[wib] = l;
    __syncthreads();

    // thread tid owns dim tid
    float ltot = s_l[0] + s_l[1] + s_l[2] + s_l[3]
               + s_l[4] + s_l[5] + s_l[6] + s_l[7];
    float acc = 0.f;
#pragma unroll
    for (int w = 0; w < 8; ++w)
        acc += s_o[w][tid];

    float xv = __ldg(x + (size_t)i * DDIM + tid);   // L1/L2 hit (row just read)
    out[(size_t)i * DDIM + tid] = fmaf(0.5f / ltot, acc, 0.5f * xv);
}

extern "C" void kernel_launch(void* const* d_in, const int* in_sizes, int n_in,
                              void* d_out, int out_size) {
    const float* x   = (const float*)d_in[0];
    const float* y   = (const float*)d_in[1];
    const float* adj = (const float*)d_in[2];
    float* out       = (float*)d_out;

    int N = in_sizes[0] / DDIM;   // 8192
    int M = in_sizes[1] / DDIM;   // 8192

    int prep_blocks = (M * 32 + 255) / 256;
    prep_y<<<prep_blocks, 256>>>(y, M);

    gat_main<<<N, 256>>>(x, adj, out, N, M);
}

// round 7
// speedup vs baseline: 1.0832x; 1.0832x over previous
#include <cuda_runtime.h>
#include <cuda_fp16.h>

#define DDIM    256
#define NMAX    8192
#define LISTCAP 768     // mean nnz ~164, sd ~12.7; 768 is absurdly safe
#define BW      4       // per-warp batch in phase B

// Scratch: RAW y rows in fp16 (4 MB, L2-resident) + reciprocal norms (fp32).
__device__ __half2 g_y16[(size_t)NMAX * (DDIM / 2)];
__device__ float   g_yinv[NMAX];

__device__ __forceinline__ float warp_sum(float v) {
#pragma unroll
    for (int off = 16; off; off >>= 1)
        v += __shfl_xor_sync(0xffffffffu, v, off);
    return v;
}

// One warp per y row: store fp16 raw copy + reciprocal norm.
__global__ void __launch_bounds__(256) prep_y(const float* __restrict__ y, int M) {
    int w    = (blockIdx.x * blockDim.x + threadIdx.x) >> 5;
    int lane = threadIdx.x & 31;
    if (w >= M) return;

    const float4* yp = (const float4*)(y + (size_t)w * DDIM);
    float4 a = yp[lane * 2];
    float4 b = yp[lane * 2 + 1];
    float ss = a.x * a.x + a.y * a.y + a.z * a.z + a.w * a.w
             + b.x * b.x + b.y * b.y + b.z * b.z + b.w * b.w;
    ss = warp_sum(ss);
    if (lane == 0) g_yinv[w] = 1.0f / fmaxf(sqrtf(ss), 1e-8f);

    __half2* o = g_y16 + (size_t)w * (DDIM / 2) + lane * 4;
    o[0] = __floats2half2_rn(a.x, a.y);
    o[1] = __floats2half2_rn(a.z, a.w);
    o[2] = __floats2half2_rn(b.x, b.y);
    o[3] = __floats2half2_rn(b.z, b.w);
}

// One CTA (256 threads, 8 warps) per output row.
// Phase A: 8 warps scan disjoint adj segments (8 float4 loads in flight each),
//          compact nonzero indices into a shared list (order-scrambled — fine).
// Phase B: warps split the neighbor list (batch 4). Dot on raw fp16 y with
//          yinv folded in pre-reduction; P@y accumulated in half2 (4 HFMA2
//          per neighbor). Cross-warp combine through smem in fp32.
__global__ void __launch_bounds__(256) gat_main(const float* __restrict__ x,
                                                const float* __restrict__ adj,
                                                float* __restrict__ out,
                                                int N, int M) {
    __shared__ unsigned short s_list[LISTCAP];
    __shared__ float s_o[8][DDIM];
    __shared__ float s_l[8];
    __shared__ int   s_cnt;

    const int i    = blockIdx.x;
    const int tid  = threadIdx.x;
    const int wib  = tid >> 5;
    const int lane = tid & 31;

    if (tid == 0) s_cnt = 0;
    __syncthreads();

    // ---- Per-warp: load + normalize x row (lane owns dims [8l, 8l+8)) ----
    const float4* xp = (const float4*)(x + (size_t)i * DDIM);
    float4 xa = xp[lane * 2];
    float4 xb = xp[lane * 2 + 1];
    float ss = xa.x * xa.x + xa.y * xa.y + xa.z * xa.z + xa.w * xa.w
             + xb.x * xb.x + xb.y * xb.y + xb.z * xb.z + xb.w * xb.w;
    ss = warp_sum(ss);
    float xinv = 1.0f / fmaxf(sqrtf(ss), 1e-8f);

    __half2 xh0 = __floats2half2_rn(xa.x * xinv, xa.y * xinv);
    __half2 xh1 = __floats2half2_rn(xa.z * xinv, xa.w * xinv);
    __half2 xh2 = __floats2half2_rn(xb.x * xinv, xb.y * xinv);
    __half2 xh3 = __floats2half2_rn(xb.z * xinv, xb.w * xinv);

    // ---- Phase A: segment scan with 8 loads in flight per warp ----
    const float* arow = adj + (size_t)i * M;
    const unsigned lt = (1u << lane) - 1u;

    for (int seg = wib * 1024; seg < M; seg += 8 * 1024) {
        float4 a[8];
#pragma unroll
        for (int u = 0; u < 8; ++u)
            a[u] = __ldcs((const float4*)(arow + seg + u * 128 + lane * 4));

#pragma unroll
        for (int u = 0; u < 8; ++u) {
            int jb = seg + u * 128 + lane * 4;
            unsigned m0 = __ballot_sync(0xffffffffu, a[u].x != 0.f);
            unsigned m1 = __ballot_sync(0xffffffffu, a[u].y != 0.f);
            unsigned m2 = __ballot_sync(0xffffffffu, a[u].z != 0.f);
            unsigned m3 = __ballot_sync(0xffffffffu, a[u].w != 0.f);
            int c0 = __popc(m0), c1 = __popc(m1), c2 = __popc(m2), c3 = __popc(m3);
            int tot = c0 + c1 + c2 + c3;
            int base = 0;
            if (tot) {
                if (lane == 0) base = atomicAdd(&s_cnt, tot);
                base = __shfl_sync(0xffffffffu, base, 0);
                if (a[u].x != 0.f) s_list[base + __popc(m0 & lt)]                = (unsigned short)(jb);
                if (a[u].y != 0.f) s_list[base + c0 + __popc(m1 & lt)]           = (unsigned short)(jb + 1);
                if (a[u].z != 0.f) s_list[base + c0 + c1 + __popc(m2 & lt)]      = (unsigned short)(jb + 2);
                if (a[u].w != 0.f) s_list[base + c0 + c1 + c2 + __popc(m3 & lt)] = (unsigned short)(jb + 3);
            }
        }
    }
    __syncthreads();
    const int cnt = s_cnt;

    // ---- Phase B: warps split neighbor list, batch 4, fp16 accumulation ----
    __half2 oh0 = __float2half2_rn(0.f);
    __half2 oh1 = oh0, oh2 = oh0, oh3 = oh0;
    float l = 0.f;

    const bool lo16 = (lane & 16) == 0;
    const bool lo8  = (lane & 8)  == 0;

    for (int base = wib * BW; base < cnt; base += 8 * BW) {
        int   jj[BW];
        uint4 v[BW];
        float d[BW], yv[BW];

        // 4 outstanding 16B L2 loads + reciprocal norms
#pragma unroll
        for (int k = 0; k < BW; ++k) {
            int idx = base + k;
            jj[k] = s_list[idx < cnt ? idx : 0];
            v[k] = *(const uint4*)(g_y16 + (size_t)jj[k] * (DDIM / 2) + lane * 4);
        }
#pragma unroll
        for (int k = 0; k < BW; ++k)
            yv[k] = __ldg(&g_yinv[jj[k]]);

        // 4 independent partial dots on raw y; fold yinv in before reduction
        // (cos = (xhat . y) / ||y||).
#pragma unroll
        for (int k = 0; k < BW; ++k) {
            __half2 acc = __hmul2(xh0, *(const __half2*)&v[k].x);
            acc = __hfma2(xh1, *(const __half2*)&v[k].y, acc);
            acc = __hfma2(xh2, *(const __half2*)&v[k].z, acc);
            acc = __hfma2(xh3, *(const __half2*)&v[k].w, acc);
            float2 af = __half22float2(acc);
            d[k] = (af.x + af.y) * yv[k];
        }

        // Packed 4-value reduction: 6 SHFLs. Value k ends in lane group 8k.
#pragma unroll
        for (int k = 0; k < 2; ++k) {
            float send = lo16 ? d[k + 2] : d[k];
            float recv = __shfl_xor_sync(0xffffffffu, send, 16);
            d[k] = (lo16 ? d[k] : d[k + 2]) + recv;
        }
        {
            float send = lo8 ? d[1] : d[0];
            float recv = __shfl_xor_sync(0xffffffffu, send, 8);
            d[0] = (lo8 ? d[0] : d[1]) + recv;
        }
        d[0] += __shfl_xor_sync(0xffffffffu, d[0], 4);
        d[0] += __shfl_xor_sync(0xffffffffu, d[0], 2);
        d[0] += __shfl_xor_sync(0xffffffffu, d[0], 1);

        float e = __expf(d[0] - 1.0f);   // one MUFU per batch

        // Broadcast weights; accumulate p*y in half2 (4 HFMA2 per neighbor).
#pragma unroll
        for (int k = 0; k < BW; ++k) {
            float ek = __shfl_sync(0xffffffffu, e, 8 * k);
            float p  = (base + k < cnt) ? ek : 0.f;
            l += p;
            __half2 ph = __float2half2_rn(p);
            oh0 = __hfma2(ph, *(const __half2*)&v[k].x, oh0);
            oh1 = __hfma2(ph, *(const __half2*)&v[k].y, oh1);
            oh2 = __hfma2(ph, *(const __half2*)&v[k].z, oh2);
            oh3 = __hfma2(ph, *(const __half2*)&v[k].w, oh3);
        }
    }

    // ---- Cross-warp combine (convert fp16 accumulators once per warp) ----
    float2 f0 = __half22float2(oh0);
    float2 f1 = __half22float2(oh1);
    float2 f2 = __half22float2(oh2);
    float2 f3 = __half22float2(oh3);
    float* so = s_o[wib] + lane * 8;
    so[0] = f0.x; so[1] = f0.y; so[2] = f1.x; so[3] = f1.y;
    so[4] = f2.x; so[5] = f2.y; so[6] = f3.x; so[7] = f3.y;
    if (lane == 0) s_l[wib] = l;
    __syncthreads();

    // thread tid owns dim tid
    float ltot = s_l[0] + s_l[1] + s_l[2] + s_l[3]
               + s_l[4] + s_l[5] + s_l[6] + s_l[7];
    float acc = 0.f;
#pragma unroll
    for (int w = 0; w < 8; ++w)
        acc += s_o[w][tid];

    float xv = __ldg(x + (size_t)i * DDIM + tid);   // L1/L2 hit (row just read)
    out[(size_t)i * DDIM + tid] = fmaf(0.5f / ltot, acc, 0.5f * xv);
}

extern "C" void kernel_launch(void* const* d_in, const int* in_sizes, int n_in,
                              void* d_out, int out_size) {
    const float* x   = (const float*)d_in[0];
    const float* y   = (const float*)d_in[1];
    const float* adj = (const float*)d_in[2];
    float* out       = (float*)d_out;

    int N = in_sizes[0] / DDIM;   // 8192
    int M = in_sizes[1] / DDIM;   // 8192

    int prep_blocks = (M * 32 + 255) / 256;
    prep_y<<<prep_blocks, 256>>>(y, M);

    gat_main<<<N, 256>>>(x, adj, out, N, M);
}

// round 8
// speedup vs baseline: 1.1078x; 1.0227x over previous
#include <cuda_runtime.h>
#include <cuda_fp16.h>

#define DDIM    256
#define NMAX    8192
#define LISTCAP 768     // mean nnz ~164, sd ~12.7; 768 is absurdly safe
#define BW      4       // per-warp batch in gat_main

// Scratch: RAW y rows in fp16 (4 MB, L2-resident) + reciprocal norms (fp32)
// + CSR-style neighbor lists built by csr_scan.
__device__ __half2        g_y16[(size_t)NMAX * (DDIM / 2)];
__device__ float          g_yinv[NMAX];
__device__ unsigned short g_list[(size_t)NMAX * LISTCAP];
__device__ int            g_cnt[NMAX];

__device__ __forceinline__ float warp_sum(float v) {
#pragma unroll
    for (int off = 16; off; off >>= 1)
        v += __shfl_xor_sync(0xffffffffu, v, off);
    return v;
}

__global__ void zero_cnt(int n) {
    int t = blockIdx.x * blockDim.x + threadIdx.x;
    if (t < n) g_cnt[t] = 0;
}

// One warp per y row: store fp16 raw copy + reciprocal norm.
__global__ void __launch_bounds__(256) prep_y(const float* __restrict__ y, int M) {
    int w    = (blockIdx.x * blockDim.x + threadIdx.x) >> 5;
    int lane = threadIdx.x & 31;
    if (w >= M) return;

    const float4* yp = (const float4*)(y + (size_t)w * DDIM);
    float4 a = yp[lane * 2];
    float4 b = yp[lane * 2 + 1];
    float ss = a.x * a.x + a.y * a.y + a.z * a.z + a.w * a.w
             + b.x * b.x + b.y * b.y + b.z * b.z + b.w * b.w;
    ss = warp_sum(ss);
    if (lane == 0) g_yinv[w] = 1.0f / fmaxf(sqrtf(ss), 1e-8f);

    __half2* o = g_y16 + (size_t)w * (DDIM / 2) + lane * 4;
    o[0] = __floats2half2_rn(a.x, a.y);
    o[1] = __floats2half2_rn(a.z, a.w);
    o[2] = __floats2half2_rn(b.x, b.y);
    o[3] = __floats2half2_rn(b.z, b.w);
}

// Dedicated streaming pass: one CTA per adj row. 8 warps scan disjoint
// 1024-col segments with 8 float4 loads in flight, ballot-compact nonzero
// column indices into the row's global list. CTA owns the row -> smem
// counter only, no global atomics. Runs at full occupancy (no phase-B
// register anchor) so the 256 MB stream hits streaming bandwidth.
__global__ void __launch_bounds__(256) csr_scan(const float* __restrict__ adj, int M) {
    __shared__ int s_cnt;
    const int row  = blockIdx.x;
    const int tid  = threadIdx.x;
    const int wib  = tid >> 5;
    const int lane = tid & 31;

    if (tid == 0) s_cnt = 0;
    __syncthreads();

    const float* arow = adj + (size_t)row * M;
    unsigned short* lst = g_list + (size_t)row * LISTCAP;
    const unsigned lt = (1u << lane) - 1u;

    for (int seg = wib * 1024; seg < M; seg += 8 * 1024) {
        float4 a[8];
#pragma unroll
        for (int u = 0; u < 8; ++u)
            a[u] = __ldcs((const float4*)(arow + seg + u * 128 + lane * 4));

#pragma unroll
        for (int u = 0; u < 8; ++u) {
            int jb = seg + u * 128 + lane * 4;
            unsigned m0 = __ballot_sync(0xffffffffu, a[u].x != 0.f);
            unsigned m1 = __ballot_sync(0xffffffffu, a[u].y != 0.f);
            unsigned m2 = __ballot_sync(0xffffffffu, a[u].z != 0.f);
            unsigned m3 = __ballot_sync(0xffffffffu, a[u].w != 0.f);
            int c0 = __popc(m0), c1 = __popc(m1), c2 = __popc(m2), c3 = __popc(m3);
            int tot = c0 + c1 + c2 + c3;
            int base = 0;
            if (tot) {
                if (lane == 0) base = atomicAdd(&s_cnt, tot);
                base = __shfl_sync(0xffffffffu, base, 0);
                if (a[u].x != 0.f) lst[base + __popc(m0 & lt)]                = (unsigned short)(jb);
                if (a[u].y != 0.f) lst[base + c0 + __popc(m1 & lt)]           = (unsigned short)(jb + 1);
                if (a[u].z != 0.f) lst[base + c0 + c1 + __popc(m2 & lt)]      = (unsigned short)(jb + 2);
                if (a[u].w != 0.f) lst[base + c0 + c1 + c2 + __popc(m3 & lt)] = (unsigned short)(jb + 3);
            }
        }
    }
    __syncthreads();
    if (tid == 0) g_cnt[row] = s_cnt;
}

// One CTA (256 threads, 8 warps) per output row — gather/softmax only.
// Stage the precomputed neighbor list into smem, then batch-4 per warp:
// fp16 dot with yinv folded pre-reduction, packed 6-SHFL reduction, fp16
// P@y accumulation, cross-warp combine through smem.
__global__ void __launch_bounds__(256) gat_main(const float* __restrict__ x,
                                                float* __restrict__ out,
                                                int N, int M) {
    __shared__ unsigned short s_list[LISTCAP];
    __shared__ float s_o[8][DDIM];
    __shared__ float s_l[8];

    const int i    = blockIdx.x;
    const int tid  = threadIdx.x;
    const int wib  = tid >> 5;
    const int lane = tid & 31;

    // ---- Stage neighbor list ----
    const int cnt = g_cnt[i];
    const unsigned short* glst = g_list + (size_t)i * LISTCAP;
    for (int t = tid; t < cnt; t += 256)
        s_list[t] = glst[t];

    // ---- Per-warp: load + normalize x row (lane owns dims [8l, 8l+8)) ----
    const float4* xp = (const float4*)(x + (size_t)i * DDIM);
    float4 xa = xp[lane * 2];
    float4 xb = xp[lane * 2 + 1];
    float ss = xa.x * xa.x + xa.y * xa.y + xa.z * xa.z + xa.w * xa.w
             + xb.x * xb.x + xb.y * xb.y + xb.z * xb.z + xb.w * xb.w;
    ss = warp_sum(ss);
    float xinv = 1.0f / fmaxf(sqrtf(ss), 1e-8f);

    __half2 xh0 = __floats2half2_rn(xa.x * xinv, xa.y * xinv);
    __half2 xh1 = __floats2half2_rn(xa.z * xinv, xa.w * xinv);
    __half2 xh2 = __floats2half2_rn(xb.x * xinv, xb.y * xinv);
    __half2 xh3 = __floats2half2_rn(xb.z * xinv, xb.w * xinv);

    __syncthreads();   // list staged

    // ---- Batched neighbor processing, fp16 accumulation ----
    __half2 oh0 = __float2half2_rn(0.f);
    __half2 oh1 = oh0, oh2 = oh0, oh3 = oh0;
    float l = 0.f;

    const bool lo16 = (lane & 16) == 0;
    const bool lo8  = (lane & 8)  == 0;

    for (int base = wib * BW; base < cnt; base += 8 * BW) {
        int   jj[BW];
        uint4 v[BW];
        float d[BW], yv[BW];

        // 4 outstanding 16B L2 loads + reciprocal norms
#pragma unroll
        for (int k = 0; k < BW; ++k) {
            int idx = base + k;
            jj[k] = s_list[idx < cnt ? idx : 0];
            v[k] = *(const uint4*)(g_y16 + (size_t)jj[k] * (DDIM / 2) + lane * 4);
        }
#pragma unroll
        for (int k = 0; k < BW; ++k)
            yv[k] = __ldg(&g_yinv[jj[k]]);

        // 4 independent partial dots on raw y; fold yinv in before reduction
#pragma unroll
        for (int k = 0; k < BW; ++k) {
            __half2 acc = __hmul2(xh0, *(const __half2*)&v[k].x);
            acc = __hfma2(xh1, *(const __half2*)&v[k].y, acc);
            acc = __hfma2(xh2, *(const __half2*)&v[k].z, acc);
            acc = __hfma2(xh3, *(const __half2*)&v[k].w, acc);
            float2 af = __half22float2(acc);
            d[k] = (af.x + af.y) * yv[k];
        }

        // Packed 4-value reduction: 6 SHFLs. Value k ends in lane group 8k.
#pragma unroll
        for (int k = 0; k < 2; ++k) {
            float send = lo16 ? d[k + 2] : d[k];
            float recv = __shfl_xor_sync(0xffffffffu, send, 16);
            d[k] = (lo16 ? d[k] : d[k + 2]) + recv;
        }
        {
            float send = lo8 ? d[1] : d[0];
            float recv = __shfl_xor_sync(0xffffffffu, send, 8);
            d[0] = (lo8 ? d[0] : d[1]) + recv;
        }
        d[0] += __shfl_xor_sync(0xffffffffu, d[0], 4);
        d[0] += __shfl_xor_sync(0xffffffffu, d[0], 2);
        d[0] += __shfl_xor_sync(0xffffffffu, d[0], 1);

        float e = __expf(d[0] - 1.0f);   // one MUFU per batch

        // Broadcast weights; accumulate p*y in half2 (4 HFMA2 per neighbor).
#pragma unroll
        for (int k = 0; k < BW; ++k) {
            float ek = __shfl_sync(0xffffffffu, e, 8 * k);
            float p  = (base + k < cnt) ? ek : 0.f;
            l += p;
            __half2 ph = __float2half2_rn(p);
            oh0 = __hfma2(ph, *(const __half2*)&v[k].x, oh0);
            oh1 = __hfma2(ph, *(const __half2*)&v[k].y, oh1);
            oh2 = __hfma2(ph, *(const __half2*)&v[k].z, oh2);
            oh3 = __hfma2(ph, *(const __half2*)&v[k].w, oh3);
        }
    }

    // ---- Cross-warp combine (convert fp16 accumulators once per warp) ----
    float2 f0 = __half22float2(oh0);
    float2 f1 = __half22float2(oh1);
    float2 f2 = __half22float2(oh2);
    float2 f3 = __half22float2(oh3);
    float* so = s_o[wib] + lane * 8;
    so[0] = f0.x; so[1] = f0.y; so[2] = f1.x; so[3] = f1.y;
    so[4] = f2.x; so[5] = f2.y; so[6] = f3.x; so[7] = f3.y;
    if (lane == 0) s_l[wib] = l;
    __syncthreads();

    // thread tid owns dim tid
    float ltot = s_l[0] + s_l[1] + s_l[2] + s_l[3]
               + s_l[4] + s_l[5] + s_l[6] + s_l[7];
    float acc = 0.f;
#pragma unroll
    for (int w = 0; w < 8; ++w)
        acc += s_o[w][tid];

    float xv = __ldg(x + (size_t)i * DDIM + tid);   // L1/L2 hit (row just read)
    out[(size_t)i * DDIM + tid] = fmaf(0.5f / ltot, acc, 0.5f * xv);
}

extern "C" void kernel_launch(void* const* d_in, const int* in_sizes, int n_in,
                              void* d_out, int out_size) {
    const float* x   = (const float*)d_in[0];
    const float* y   = (const float*)d_in[1];
    const float* adj = (const float*)d_in[2];
    float* out       = (float*)d_out;

    int N = in_sizes[0] / DDIM;   // 8192
    int M = in_sizes[1] / DDIM;   // 8192

    zero_cnt<<<(NMAX + 255) / 256, 256>>>(NMAX);

    int prep_blocks = (M * 32 + 255) / 256;
    prep_y<<<prep_blocks, 256>>>(y, M);

    csr_scan<<<N, 256>>>(adj, M);

    gat_main<<<N, 256>>>(x, out, N, M);
}